// round 1
// baseline (speedup 1.0000x reference)
#include <cuda_runtime.h>
#include <cstdint>

typedef unsigned long long u64;

#define A_NODES 256
#define F_DIM   256
#define C_DIM   32

// ---------------- scratch (device globals; no allocation allowed) -------------
__device__ float g_leftT[C_DIM * A_NODES];              // [c][a]  (transposed for LDS.128 over a)
__device__ float g_right[A_NODES * C_DIM];              // [b][d]
__device__ float g_T[(size_t)A_NODES * C_DIM * F_DIM];  // [b][c][f]  8 MB

// ---------------- f32x2 helpers ----------------------------------------------
__device__ __forceinline__ u64 pack2(float x, float y) {
    u64 r;
    asm("mov.b64 %0, {%1, %2};" : "=l"(r) : "f"(x), "f"(y));
    return r;
}
__device__ __forceinline__ void fma2(u64& d, u64 a, u64 b) {
    asm("fma.rn.f32x2 %0, %1, %2, %0;" : "+l"(d) : "l"(a), "l"(b));
}
__device__ __forceinline__ float2 unpack2(u64 v) {
    float2 f;
    asm("mov.b64 {%0, %1}, %2;" : "=f"(f.x), "=f"(f.y) : "l"(v));
    return f;
}

// ---------------- Kernel A: LayerNorm + dual projections ----------------------
// grid 256 (one block per node), 256 threads
__global__ void k_lnproj(const float* __restrict__ nv, const float* __restrict__ mask,
                         const float* __restrict__ lns, const float* __restrict__ lnb,
                         const float* __restrict__ Wl, const float* __restrict__ bl,
                         const float* __restrict__ Wr, const float* __restrict__ br) {
    int a = blockIdx.x, t = threadIdx.x;
    __shared__ float act[F_DIM];
    __shared__ float red[16];
    __shared__ float pls[256], prs[256];
    __shared__ float s_mu, s_rs;

    float x = nv[a * F_DIM + t];
    float s = x, s2 = x * x;
    #pragma unroll
    for (int o = 16; o; o >>= 1) {
        s  += __shfl_xor_sync(0xffffffffu, s,  o);
        s2 += __shfl_xor_sync(0xffffffffu, s2, o);
    }
    if ((t & 31) == 0) { red[t >> 5] = s; red[8 + (t >> 5)] = s2; }
    __syncthreads();
    if (t == 0) {
        float S = 0.f, S2 = 0.f;
        #pragma unroll
        for (int i = 0; i < 8; i++) { S += red[i]; S2 += red[8 + i]; }
        float m = S * (1.0f / F_DIM);
        float v = S2 * (1.0f / F_DIM) - m * m;
        s_mu = m;
        s_rs = rsqrtf(v + 1e-5f);
    }
    __syncthreads();
    act[t] = (x - s_mu) * s_rs * lns[t] + lnb[t];
    __syncthreads();

    // projections: thread (c = t&31, chunk = t>>5 over f)
    int c = t & 31, ch = t >> 5;
    float pl = 0.f, pr = 0.f;
    #pragma unroll
    for (int k = 0; k < 32; k++) {
        int f = ch * 32 + k;
        float av = act[f];
        pl = fmaf(av, Wl[f * C_DIM + c], pl);
        pr = fmaf(av, Wr[f * C_DIM + c], pr);
    }
    pls[t] = pl; prs[t] = pr;
    __syncthreads();
    if (t < 32) {
        float L = bl[t], R = br[t];
        #pragma unroll
        for (int k = 0; k < 8; k++) { L += pls[k * 32 + t]; R += prs[k * 32 + t]; }
        float m = mask[a];
        g_leftT[t * A_NODES + a] = L * m;   // transposed [c][a]
        g_right[a * C_DIM + t]   = R * m;   // [b][d]
    }
}

// ---------------- Kernel B: T[b,c,f] = sum_d right[b,d] * Wo[c*32+d, f] -------
// grid (32 c, 8 b-tiles of 32), 256 threads (f). f32x2 packed over b.
__global__ void __launch_bounds__(256, 2) k_makeT(const float* __restrict__ Wo) {
    int c  = blockIdx.x;
    int b0 = blockIdx.y * 32;
    int f  = threadIdx.x;

    __shared__ __align__(16) float rT[32 * 32];   // rT[d][b_local]

    u64 w2[32];
    #pragma unroll
    for (int d = 0; d < 32; d++) {
        float wv = Wo[(size_t)(c * 32 + d) * F_DIM + f];
        w2[d] = pack2(wv, wv);
    }
    for (int i = f; i < 1024; i += 256) {
        int d = i >> 5, bl_ = i & 31;
        rT[d * 32 + bl_] = g_right[(b0 + bl_) * C_DIM + d];
    }
    __syncthreads();

    #pragma unroll
    for (int bq = 0; bq < 32; bq += 4) {
        u64 a0 = 0ULL, a1 = 0ULL;
        #pragma unroll
        for (int d = 0; d < 32; d++) {
            ulonglong2 r2 = *(const ulonglong2*)&rT[d * 32 + bq];
            fma2(a0, r2.x, w2[d]);
            fma2(a1, r2.y, w2[d]);
        }
        float2 v0 = unpack2(a0), v1 = unpack2(a1);
        float* p = g_T + (size_t)(b0 + bq) * (C_DIM * F_DIM) + c * F_DIM + f;
        p[0]                    = v0.x;
        p[1 * C_DIM * F_DIM]    = v0.y;
        p[2 * C_DIM * F_DIM]    = v1.x;
        p[3 * C_DIM * F_DIM]    = v1.y;
    }
}

// ---------------- Kernel C: out[a,b,f] = bo[f] + sum_c left[a,c] * T[b,c,f] ---
// grid 256 (one block per b), 256 threads (f). f32x2 packed over a,
// left quads via LDS.128 (zero splat instructions in hot loop).
__global__ void __launch_bounds__(256, 2) k_outer(const float* __restrict__ bo,
                                                  float* __restrict__ out) {
    int b = blockIdx.x, f = threadIdx.x;
    __shared__ __align__(16) float lT[C_DIM * A_NODES];   // 32 KB, [c][a]

    for (int i = f; i < C_DIM * A_NODES; i += 256) lT[i] = g_leftT[i];

    // T[b,:,f] splatted into 32 packed registers (loop-invariant over a)
    u64 t2[32];
    const float* Tb = g_T + (size_t)b * (C_DIM * F_DIM);
    #pragma unroll
    for (int c = 0; c < 32; c++) {
        float tv = Tb[c * F_DIM + f];
        t2[c] = pack2(tv, tv);
    }
    u64 bo2;
    { float bv = bo[f]; bo2 = pack2(bv, bv); }
    __syncthreads();

    float* outb = out + (size_t)b * F_DIM + f;   // + a*65536 per row
    #pragma unroll 2
    for (int a = 0; a < A_NODES; a += 4) {
        u64 acc0 = bo2, acc1 = bo2;
        #pragma unroll
        for (int c = 0; c < 32; c++) {
            ulonglong2 l2 = *(const ulonglong2*)&lT[c * A_NODES + a];
            fma2(acc0, l2.x, t2[c]);
            fma2(acc1, l2.y, t2[c]);
        }
        float2 v0 = unpack2(acc0), v1 = unpack2(acc1);
        float* p = outb + (size_t)a * (A_NODES * F_DIM);
        p[0]                          = v0.x;
        p[1 * A_NODES * F_DIM]        = v0.y;
        p[2 * (size_t)A_NODES * F_DIM] = v1.x;
        p[3 * (size_t)A_NODES * F_DIM] = v1.y;
    }
}

// ---------------- launch ------------------------------------------------------
extern "C" void kernel_launch(void* const* d_in, const int* in_sizes, int n_in,
                              void* d_out, int out_size) {
    const float* nv   = (const float*)d_in[0];
    const float* mask = (const float*)d_in[1];
    const float* lns  = (const float*)d_in[2];
    const float* lnb  = (const float*)d_in[3];
    const float* Wl   = (const float*)d_in[4];
    const float* bl   = (const float*)d_in[5];
    const float* Wr   = (const float*)d_in[6];
    const float* br   = (const float*)d_in[7];
    const float* Wo   = (const float*)d_in[8];
    const float* bo   = (const float*)d_in[9];
    float* out = (float*)d_out;

    k_lnproj<<<A_NODES, 256>>>(nv, mask, lns, lnb, Wl, bl, Wr, br);
    k_makeT<<<dim3(32, 8), 256>>>(Wo);
    k_outer<<<A_NODES, 256>>>(bo, out);
}

// round 3
// speedup vs baseline: 1.3950x; 1.3950x over previous
#include <cuda_runtime.h>
#include <cuda_bf16.h>
#include <cstdint>

typedef unsigned long long u64;
typedef unsigned int u32;
typedef unsigned short u16;

#define A_NODES 256
#define F_DIM   256
#define C_DIM   32

// ---------------- scratch (device globals; no runtime allocation) ------------
__device__ float g_right[A_NODES * C_DIM];                    // [b][d]
__device__ float g_T[(size_t)A_NODES * C_DIM * F_DIM];        // [b][c][f] fp32, 8 MB
__device__ __nv_bfloat16 g_Aop[A_NODES * 64];                 // [a][0:32 lh | 32:64 ll]

// ---------------- f32x2 helpers ----------------------------------------------
__device__ __forceinline__ u64 pack2(float x, float y) {
    u64 r; asm("mov.b64 %0, {%1, %2};" : "=l"(r) : "f"(x), "f"(y)); return r;
}
__device__ __forceinline__ void fma2(u64& d, u64 a, u64 b) {
    asm("fma.rn.f32x2 %0, %1, %2, %0;" : "+l"(d) : "l"(a), "l"(b));
}
__device__ __forceinline__ float2 unpack2(u64 v) {
    float2 f; asm("mov.b64 {%0, %1}, %2;" : "=f"(f.x), "=f"(f.y) : "l"(v)); return f;
}

// ---------------- mma.sync bf16 (no 'a'-target features needed) ---------------
__device__ __forceinline__ void mma_bf16(float* d, const u32* a, const u32* b) {
    asm volatile("mma.sync.aligned.m16n8k16.row.col.f32.bf16.bf16.f32 "
        "{%0,%1,%2,%3}, {%4,%5,%6,%7}, {%8,%9}, {%0,%1,%2,%3};"
        : "+f"(d[0]), "+f"(d[1]), "+f"(d[2]), "+f"(d[3])
        : "r"(a[0]), "r"(a[1]), "r"(a[2]), "r"(a[3]), "r"(b[0]), "r"(b[1]));
}

// ---------------- Kernel A: LayerNorm + dual projections ----------------------
__global__ void k_lnproj(const float* __restrict__ nv, const float* __restrict__ mask,
                         const float* __restrict__ lns, const float* __restrict__ lnb,
                         const float* __restrict__ Wl, const float* __restrict__ bl,
                         const float* __restrict__ Wr, const float* __restrict__ br) {
    int a = blockIdx.x, t = threadIdx.x;
    __shared__ float act[F_DIM];
    __shared__ float red[16];
    __shared__ float pls[256], prs[256];
    __shared__ float s_mu, s_rs;

    float x = nv[a * F_DIM + t];
    float s = x, s2 = x * x;
    #pragma unroll
    for (int o = 16; o; o >>= 1) {
        s  += __shfl_xor_sync(0xffffffffu, s,  o);
        s2 += __shfl_xor_sync(0xffffffffu, s2, o);
    }
    if ((t & 31) == 0) { red[t >> 5] = s; red[8 + (t >> 5)] = s2; }
    __syncthreads();
    if (t == 0) {
        float S = 0.f, S2 = 0.f;
        #pragma unroll
        for (int i = 0; i < 8; i++) { S += red[i]; S2 += red[8 + i]; }
        float m = S * (1.0f / F_DIM);
        float v = S2 * (1.0f / F_DIM) - m * m;
        s_mu = m;
        s_rs = rsqrtf(v + 1e-5f);
    }
    __syncthreads();
    act[t] = (x - s_mu) * s_rs * lns[t] + lnb[t];
    __syncthreads();

    int c = t & 31, ch = t >> 5;
    float pl = 0.f, pr = 0.f;
    #pragma unroll
    for (int k = 0; k < 32; k++) {
        int f = ch * 32 + k;
        float av = act[f];
        pl = fmaf(av, Wl[f * C_DIM + c], pl);
        pr = fmaf(av, Wr[f * C_DIM + c], pr);
    }
    pls[t] = pl; prs[t] = pr;
    __syncthreads();
    if (t < 32) {
        float L = bl[t], R = br[t];
        #pragma unroll
        for (int k = 0; k < 8; k++) { L += pls[k * 32 + t]; R += prs[k * 32 + t]; }
        float m = mask[a];
        g_right[a * C_DIM + t] = R * m;
        float Lm = L * m;
        __nv_bfloat16 lh = __float2bfloat16(Lm);
        __nv_bfloat16 ll = __float2bfloat16(Lm - __bfloat162float(lh));
        g_Aop[a * 64 + t]      = lh;
        g_Aop[a * 64 + 32 + t] = ll;
    }
}

// ---------------- Kernel B: T[b,c,f] = sum_d right[b,d] * Wo[c*32+d, f] -------
__global__ void __launch_bounds__(256, 2) k_makeT(const float* __restrict__ Wo) {
    int c  = blockIdx.x;
    int b0 = blockIdx.y * 32;
    int f  = threadIdx.x;

    __shared__ __align__(16) float rT[32 * 32];

    u64 w2[32];
    #pragma unroll
    for (int d = 0; d < 32; d++) {
        float wv = Wo[(size_t)(c * 32 + d) * F_DIM + f];
        w2[d] = pack2(wv, wv);
    }
    for (int i = f; i < 1024; i += 256) {
        int d = i >> 5, bl_ = i & 31;
        rT[d * 32 + bl_] = g_right[(b0 + bl_) * C_DIM + d];
    }
    __syncthreads();

    #pragma unroll
    for (int bq = 0; bq < 32; bq += 4) {
        u64 a0 = 0ULL, a1 = 0ULL;
        #pragma unroll
        for (int d = 0; d < 32; d++) {
            ulonglong2 r2 = *(const ulonglong2*)&rT[d * 32 + bq];
            fma2(a0, r2.x, w2[d]);
            fma2(a1, r2.y, w2[d]);
        }
        float2 v0 = unpack2(a0), v1 = unpack2(a1);
        float* p = g_T + (size_t)(b0 + bq) * (C_DIM * F_DIM) + c * F_DIM + f;
        p[0]                     = v0.x;
        p[1 * C_DIM * F_DIM]     = v0.y;
        p[2 * C_DIM * F_DIM]     = v1.x;
        p[3 * C_DIM * F_DIM]     = v1.y;
    }
}

// ---------------- Kernel C: mma.sync GEMM  out[a, b*256+f] --------------------
// Per CTA: one b, tile M=128(a) x N=128(f), K=32 with 3 bf16 correction passes.
// A_s[m][k64] (hi|lo), B_s[f][k64] (hi|lo), both row stride 72 bf16 (conflict-free
// fragment LDS: bank = 4*g + tig).
#define LDA 72
#define LDB 72

__global__ void __launch_bounds__(256, 2) k_gemm(const float* __restrict__ bo,
                                                 float* __restrict__ out) {
    __shared__ __align__(16) u16 A_s[128 * LDA];
    __shared__ __align__(16) u16 B_s[128 * LDB];
    __shared__ float bo_s[128];

    int b  = blockIdx.x;
    int mt = blockIdx.y;
    int nt = blockIdx.z;
    int t = threadIdx.x, w = t >> 5, lane = t & 31;
    int g = lane >> 2, tig = lane & 3;
    int wm = w >> 2, wn = w & 3;           // warp tile: rows wm*64, cols wn*32
    int m0 = wm * 64, n0 = wn * 32;

    // --- load A tile (128 x 64 bf16, already hi|lo packed) ---
    #pragma unroll
    for (int i = 0; i < 4; i++) {
        int id = t + 256 * i;
        int m = id >> 3, q = id & 7;
        uint4 v = *(const uint4*)(g_Aop + ((size_t)mt * 128 + m) * 64 + q * 8);
        *(uint4*)(&A_s[m * LDA + q * 8]) = v;
    }

    // --- load B tile: g_T[b][c][nt*128 + f] fp32 -> split -> B_s[f][c | 32+c] ---
    const float* Tb = g_T + (size_t)b * (C_DIM * F_DIM) + nt * 128;
    #pragma unroll
    for (int j = 0; j < 16; j++) {
        int idx = t + 256 * j;
        int c = idx >> 7, f = idx & 127;
        float v = Tb[c * F_DIM + f];
        __nv_bfloat16 h = __float2bfloat16(v);
        __nv_bfloat16 l = __float2bfloat16(v - __bfloat162float(h));
        B_s[f * LDB + c]      = __bfloat16_as_ushort(h);
        B_s[f * LDB + 32 + c] = __bfloat16_as_ushort(l);
    }
    if (t < 128) bo_s[t] = bo[nt * 128 + t];
    __syncthreads();

    float acc[4][4][4];
    #pragma unroll
    for (int mi = 0; mi < 4; mi++)
        #pragma unroll
        for (int ni = 0; ni < 4; ni++)
            #pragma unroll
            for (int q = 0; q < 4; q++) acc[mi][ni][q] = 0.f;

    // (ka, kb) pairs: hi*hi (k=0,16), lo*hi, hi*lo
    const int KA[6] = {0, 16, 32, 48, 0, 16};
    const int KB[6] = {0, 16, 0, 16, 32, 48};

    #pragma unroll
    for (int kp = 0; kp < 6; kp++) {
        int ka = KA[kp], kb = KB[kp];
        u32 af[4][4], bfr[4][2];
        #pragma unroll
        for (int mi = 0; mi < 4; mi++) {
            const u16* base = &A_s[(m0 + mi * 16 + g) * LDA + ka + tig * 2];
            af[mi][0] = *(const u32*)(base);
            af[mi][1] = *(const u32*)(base + 8 * LDA);
            af[mi][2] = *(const u32*)(base + 8);
            af[mi][3] = *(const u32*)(base + 8 * LDA + 8);
        }
        #pragma unroll
        for (int ni = 0; ni < 4; ni++) {
            const u16* base = &B_s[(n0 + ni * 8 + g) * LDB + kb + tig * 2];
            bfr[ni][0] = *(const u32*)(base);
            bfr[ni][1] = *(const u32*)(base + 8);
        }
        #pragma unroll
        for (int mi = 0; mi < 4; mi++)
            #pragma unroll
            for (int ni = 0; ni < 4; ni++)
                mma_bf16(acc[mi][ni], af[mi], bfr[ni]);
    }

    // --- epilogue: out[a][b][f] + bo[f] ---
    #pragma unroll
    for (int mi = 0; mi < 4; mi++) {
        size_t a_row = (size_t)mt * 128 + m0 + mi * 16 + g;
        float* prow = out + a_row * ((size_t)A_NODES * F_DIM) + (size_t)b * F_DIM + nt * 128;
        #pragma unroll
        for (int ni = 0; ni < 4; ni++) {
            int fl = n0 + ni * 8 + tig * 2;
            float bx = bo_s[fl], by = bo_s[fl + 1];
            float2 v0 = make_float2(acc[mi][ni][0] + bx, acc[mi][ni][1] + by);
            float2 v1 = make_float2(acc[mi][ni][2] + bx, acc[mi][ni][3] + by);
            *(float2*)(prow + fl) = v0;
            *(float2*)(prow + 8 * ((size_t)A_NODES * F_DIM) + fl) = v1;
        }
    }
}

// ---------------- launch ------------------------------------------------------
extern "C" void kernel_launch(void* const* d_in, const int* in_sizes, int n_in,
                              void* d_out, int out_size) {
    const float* nv   = (const float*)d_in[0];
    const float* mask = (const float*)d_in[1];
    const float* lns  = (const float*)d_in[2];
    const float* lnb  = (const float*)d_in[3];
    const float* Wl   = (const float*)d_in[4];
    const float* bl   = (const float*)d_in[5];
    const float* Wr   = (const float*)d_in[6];
    const float* br   = (const float*)d_in[7];
    const float* Wo   = (const float*)d_in[8];
    const float* bo   = (const float*)d_in[9];
    float* out = (float*)d_out;

    k_lnproj<<<A_NODES, 256>>>(nv, mask, lns, lnb, Wl, bl, Wr, br);
    k_makeT<<<dim3(32, 8), 256>>>(Wo);
    k_gemm<<<dim3(256, 2, 2), 256>>>(bo, out);
}